// round 12
// baseline (speedup 1.0000x reference)
#include <cuda_runtime.h>
#include <math.h>

#define Bv 1024
#define Sv 2048
#define Dv 64
#define Hv 4
#define HDv 16

#define NSTAGE 16      // smem ring stages per warp (power of 2)
#define LOOKAHEAD 15   // chunks in flight (chunk = 2 rows = 512B)

// Scratch (no cudaMalloc allowed) — static device globals.
__device__ float g_hbuf[Bv * 128];        // relu(value @ w_a1.T + b_a1)
__device__ float g_wvbuf[Bv * Dv];        // write_value per batch
__device__ float g_ebuf[(size_t)Bv * Sv]; // NORMALIZED address a[b,s]

__device__ __forceinline__ void cp_async16(void* smem_dst, const void* gsrc) {
    unsigned sd = (unsigned)__cvta_generic_to_shared(smem_dst);
    asm volatile("cp.async.cg.shared.global [%0], [%1], 16;\n"
                 :: "r"(sd), "l"(gsrc) : "memory");
}
#define CP_COMMIT()  asm volatile("cp.async.commit_group;\n" ::: "memory")
#define CP_WAIT14() asm volatile("cp.async.wait_group 14;\n" ::: "memory")
#define CP_WAIT0()   asm volatile("cp.async.wait_group 0;\n" ::: "memory")

// ---- packed f32x2 helpers (sm_103a paired-FP32 pipe) ----
typedef unsigned long long u64t;
__device__ __forceinline__ u64t pk2(float a, float b) {
    u64t r; asm("mov.b64 %0, {%1, %2};" : "=l"(r) : "f"(a), "f"(b)); return r;
}
__device__ __forceinline__ void unpk2(float& a, float& b, u64t p) {
    asm("mov.b64 {%0, %1}, %2;" : "=f"(a), "=f"(b) : "l"(p));
}
__device__ __forceinline__ u64t mul2(u64t a, u64t b) {
    u64t r; asm("mul.rn.f32x2 %0, %1, %2;" : "=l"(r) : "l"(a), "l"(b)); return r;
}
__device__ __forceinline__ void fma2(u64t& d, u64t a, u64t b) {
    asm("fma.rn.f32x2 %0, %1, %2, %0;" : "+l"(d) : "l"(a), "l"(b));
}

#define LOG2E 1.4426950408889634f

// ---------------------------------------------------------------------------
// K1 (R11): R8's verified 16-lane/4-dim compute core + R7's verified cp.async
// ring + 3 CTAs/SM (24 warps — the untested lever). One CTA per batch, 256
// threads = 8 warps. Warp w owns rows [w*256,+256) as 128 chunks of 2 rows;
// warp splits into 2 groups of 16 (grp = lane>>4), group handles one row per
// chunk; lane owns dims [4*l15, 4*l15+4) (l15 = lane&15) — ONE float4 per
// lane per chunk. Per-warp private 16-stage ring (stage = 128 floats, no
// padding needed: all 4 LDS phases conflict-free). Each lane cp.asyncs
// exactly the float4 it later reads -> wait_group alone gives visibility;
// no barriers in the main loop. Low registers (qk2 16 + u2 16) fit the
// 84-reg budget of 3 CTAs/SM.
// ---------------------------------------------------------------------------
__global__ __launch_bounds__(256, 3) void k1_attn(
    const float* __restrict__ query, const float* __restrict__ sp,
    const float* __restrict__ wq, const float* __restrict__ wk,
    const float* __restrict__ wv, const float* __restrict__ bq,
    const float* __restrict__ bk, const float* __restrict__ bv,
    const float* __restrict__ wo, const float* __restrict__ bo,
    const float* __restrict__ w_write, const float* __restrict__ b_write,
    const float* __restrict__ w_a1, const float* __restrict__ b_a1)
{
    extern __shared__ float dyn[];   // 8 warps * 16 stages * 128 floats = 64KB
                                     // aliased as partial-combine buffer after loop
    __shared__ float s_q[Dv];
    __shared__ float s_qv[Dv];
    __shared__ float s_qk[Hv * Dv];
    __shared__ float s_c[Hv];
    __shared__ float s_pl[16 * Hv];
    __shared__ float s_wvec[Hv * Dv];
    __shared__ float s_ctx[Dv];
    __shared__ float s_val[Dv];

    const int b = blockIdx.x;
    const int t = threadIdx.x;
    const int warp = t >> 5, lane = t & 31;
    const int grp = lane >> 4;              // which row of the chunk
    const int l15 = lane & 15;              // lane within 16-lane row group
    const int base = lane & 3;              // head this lane owns post-reduction
    const float* spb = sp + (size_t)b * Sv * Dv;

    float* wbase = dyn + warp * (NSTAGE * 128);     // this warp's private ring
    float* lslot = wbase + grp * 64 + 4 * l15;      // lane's slot (per stage)
    // lane's stream: row (warp*256 + 2c + grp), dims [4*l15, 4*l15+4)
    const float* lsrc = spb + ((size_t)warp * 256 + grp) * 64 + 4 * l15;

    // ---- prologue: issue chunks 0..14 (1 cp.async of 16B per lane each) ----
#pragma unroll
    for (int c = 0; c < LOOKAHEAD; c++) {
        cp_async16(lslot + c * 128, lsrc + (size_t)c * 128);
        CP_COMMIT();
    }

    // ---- q projection (overlaps with in-flight loads) ----
    if (t < Dv) s_q[t] = query[(size_t)b * Dv + t];
    __syncthreads();
    if (t < Dv) {
        float acc = bq[t];
        const float* wr = wq + t * Dv;
#pragma unroll
        for (int j = 0; j < Dv; j++) acc += __ldg(wr + j) * s_q[j];
        s_qv[t] = acc;
    }
    __syncthreads();

    // ---- folded score vectors: qk_h[j] = 0.25 * sum_t qv[16h+t]*wk[16h+t,j] ----
    {
        const int h = t >> 6, j = t & 63;
        float acc = 0.f;
#pragma unroll
        for (int tt = 0; tt < HDv; tt++)
            acc += s_qv[h * HDv + tt] * __ldg(&wk[(h * HDv + tt) * Dv + j]);
        s_qk[h * Dv + j] = 0.25f * acc;
        if (t < Hv) {
            float c = 0.f;
#pragma unroll
            for (int tt = 0; tt < HDv; tt++) c += s_qv[t * HDv + tt] * __ldg(&bk[t * HDv + tt]);
            s_c[t] = 0.25f * c;
        }
    }
    __syncthreads();

    // per-lane folded vectors: 4 dims x 4 heads, packed (16 regs)
    u64t qk2[Hv][2];
#pragma unroll
    for (int h = 0; h < Hv; h++) {
        qk2[h][0] = pk2(s_qk[h * Dv + 4 * l15 + 0], s_qk[h * Dv + 4 * l15 + 1]);
        qk2[h][1] = pk2(s_qk[h * Dv + 4 * l15 + 2], s_qk[h * Dv + 4 * l15 + 3]);
    }
    const float cprem = s_c[base] * LOG2E;
    const bool bit0 = (lane & 1) != 0;
    const bool bit1 = (lane & 2) != 0;

    u64t u2[Hv][2];                          // u2[j] accumulates head (base^j), lane's 4 dims
    float ls[Hv];                            // ls[j]  accumulates head (base^j)
#pragma unroll
    for (int j = 0; j < Hv; j++) {
        ls[j] = 0.f;
        u2[j][0] = 0ull; u2[j][1] = 0ull;
    }

    // ---- main loop: 128 chunks (2 rows each), per-warp pipeline, NO barriers ----
#pragma unroll 1
    for (int c = 0; c < 128; c++) {
        CP_WAIT14();                     // chunk c complete for THIS thread

        const int nc = c + LOOKAHEAD;    // issue chunk c+15 first
        if (nc < 128)
            cp_async16(lslot + (nc & 15) * 128, lsrc + (size_t)nc * 128);
        CP_COMMIT();                     // uniform group count even when empty

        float4 x = *(const float4*)(wbase + (c & 15) * 128 + grp * 64 + 4 * l15);
        u64t xp0 = pk2(x.x, x.y), xp1 = pk2(x.z, x.w);

        // score partials: v[h] = dot(qk[h], x) over this lane's 4 dims
        float v[Hv];
#pragma unroll
        for (int h = 0; h < Hv; h++) {
            u64t acc = mul2(qk2[h][0], xp0);
            fma2(acc, qk2[h][1], xp1);
            float lo, hi; unpk2(lo, hi, acc);
            v[h] = lo + hi;
        }

        // reduce-scatter over 16 lanes -> lane holds full score of head (lane&3)
        // (verbatim from R8 — verified correct at rel_err 4.7e-8)
        float send0 = bit0 ? v[0] : v[1];
        float send1 = bit0 ? v[2] : v[3];
        float r0 = __shfl_xor_sync(0xffffffffu, send0, 1);
        float r1 = __shfl_xor_sync(0xffffffffu, send1, 1);
        float a0 = (bit0 ? v[1] : v[0]) + r0;   // head bit0
        float a1 = (bit0 ? v[3] : v[2]) + r1;   // head 2+bit0
        float send2 = bit1 ? a0 : a1;
        float r2 = __shfl_xor_sync(0xffffffffu, send2, 2);
        float s = (bit1 ? a1 : a0) + r2;        // head base, quad partial
        s += __shfl_xor_sync(0xffffffffu, s, 4);
        s += __shfl_xor_sync(0xffffffffu, s, 8);

        // exp once per head, 3-SHFL allgather: q[j] = p(head base^j)
        float q0 = exp2f(__fmaf_rn(s, LOG2E, cprem));
        float q1 = __shfl_xor_sync(0xffffffffu, q0, 1);
        float q2 = __shfl_xor_sync(0xffffffffu, q0, 2);
        float q3 = __shfl_xor_sync(0xffffffffu, q1, 2);
        float q[4] = {q0, q1, q2, q3};

#pragma unroll
        for (int j = 0; j < Hv; j++) {
            ls[j] += q[j];
            u64t qq = pk2(q[j], q[j]);
            fma2(u2[j][0], qq, xp0);
            fma2(u2[j][1], qq, xp1);
        }
    }
    CP_WAIT0();
    __syncthreads();

    // ---- combine 16 group partials (dyn aliased; needs 4096 floats) ----
    // u2[j]/ls[j] correspond to REAL head (base^j): permute on store.
    float* s_part = dyn;
    const int pg = warp * 2 + grp;           // 16 row groups
    if (l15 == 0) {                          // base=0 -> identity permutation
#pragma unroll
        for (int j = 0; j < Hv; j++) s_pl[pg * 4 + j] = ls[j];
    }
#pragma unroll
    for (int j = 0; j < Hv; j++) {
        const int h = base ^ j;              // real head
        float l0, h0, l1, h1;
        unpk2(l0, h0, u2[j][0]);
        unpk2(l1, h1, u2[j][1]);
        float* pp = &s_part[(pg * 4 + h) * 64 + 4 * l15];
        pp[0] = l0; pp[1] = h0; pp[2] = l1; pp[3] = h1;
    }
    __syncthreads();
    {
        const int h = t >> 6, d = t & 63;
        float U = 0.f;
#pragma unroll
        for (int p = 0; p < 16; p++) U += s_part[(p * 4 + h) * 64 + d];
        float L = 0.f;
#pragma unroll
        for (int p = 0; p < 16; p++) L += s_pl[p * 4 + h];
        s_wvec[h * 64 + d] = U / L;          // attn-weighted mean of sp rows
    }
    __syncthreads();

    // ---- tiny per-batch matvec chain (weights straight from global/L2) ----
    if (t < Dv) {
        float acc = bv[t];
        const int h = t >> 4;
        const float* wr = wv + t * Dv;
#pragma unroll
        for (int j = 0; j < Dv; j++) acc += __ldg(wr + j) * s_wvec[h * 64 + j];
        s_ctx[t] = acc;
    }
    __syncthreads();
    if (t < Dv) {
        float acc = bo[t];
        const float* wr = wo + t * Dv;
#pragma unroll
        for (int j = 0; j < Dv; j++) acc += __ldg(wr + j) * s_ctx[j];
        s_val[t] = acc;
    }
    __syncthreads();
    if (t < 128) {
        float acc = b_a1[t];
        const float* wr = w_a1 + t * Dv;
#pragma unroll
        for (int j = 0; j < Dv; j++) acc += __ldg(wr + j) * s_val[j];
        g_hbuf[(size_t)b * 128 + t] = fmaxf(acc, 0.f);
    }
    if (t >= 128 && t < 128 + Dv) {
        const int o = t - 128;
        float acc = b_write[o];
        const float* wr = w_write + o * Dv;
#pragma unroll
        for (int j = 0; j < Dv; j++) acc += __ldg(wr + j) * s_val[j];
        g_wvbuf[(size_t)b * Dv + o] = acc;
    }
}

// ---------------------------------------------------------------------------
// K2: address logits GEMM (1024 x 2048 x 128) + softmax. Writes NORMALIZED
// address a[b,s] into g_ebuf (the CTA owns the full per-batch denominator).
// ---------------------------------------------------------------------------
__global__ __launch_bounds__(256) void k2_addr(const float* __restrict__ w_a2,
                                               const float* __restrict__ b_a2)
{
    const int b0 = blockIdx.x * 8;
    const int t = threadIdx.x;
    __shared__ float hs[8 * 128];
    __shared__ float sden[8];

    for (int idx = t; idx < 1024; idx += 256) hs[idx] = g_hbuf[(size_t)b0 * 128 + idx];
    if (t < 8) sden[t] = 0.f;
    __syncthreads();

    float acc[8][8];
#pragma unroll
    for (int r = 0; r < 8; r++)
#pragma unroll
        for (int bb = 0; bb < 8; bb++) acc[r][bb] = 0.f;

    const float4* w4 = (const float4*)w_a2;
    const float4* h4 = (const float4*)hs;
#pragma unroll 1
    for (int k8 = 0; k8 < 16; k8++) {
        float4 ha[8], hb[8];
#pragma unroll
        for (int bb = 0; bb < 8; bb++) {
            ha[bb] = h4[bb * 32 + 2 * k8];
            hb[bb] = h4[bb * 32 + 2 * k8 + 1];
        }
#pragma unroll
        for (int r = 0; r < 8; r++) {
            const int s = t + 256 * r;
            float4 wa = w4[(size_t)s * 32 + 2 * k8];
            float4 wb = w4[(size_t)s * 32 + 2 * k8 + 1];
#pragma unroll
            for (int bb = 0; bb < 8; bb++) {
                acc[r][bb] += wa.x * ha[bb].x + wa.y * ha[bb].y +
                              wa.z * ha[bb].z + wa.w * ha[bb].w +
                              wb.x * hb[bb].x + wb.y * hb[bb].y +
                              wb.z * hb[bb].z + wb.w * hb[bb].w;
            }
        }
    }

    // pass 1: per-batch exp-sum (logits small -> safe without max-sub)
    float psum[8];
#pragma unroll
    for (int bb = 0; bb < 8; bb++) psum[bb] = 0.f;
#pragma unroll
    for (int r = 0; r < 8; r++) {
        const float ba = b_a2[t + 256 * r];
#pragma unroll
        for (int bb = 0; bb < 8; bb++) psum[bb] += __expf(acc[r][bb] + ba);
    }
#pragma unroll
    for (int off = 16; off; off >>= 1)
#pragma unroll
        for (int bb = 0; bb < 8; bb++)
            psum[bb] += __shfl_xor_sync(0xffffffffu, psum[bb], off);
    if ((t & 31) == 0) {
#pragma unroll
        for (int bb = 0; bb < 8; bb++) atomicAdd(&sden[bb], psum[bb]);
    }
    __syncthreads();

    float inv[8];
#pragma unroll
    for (int bb = 0; bb < 8; bb++) inv[bb] = 1.f / sden[bb];

    // pass 2: recompute exp (deterministic), write normalized a
#pragma unroll
    for (int r = 0; r < 8; r++) {
        const int s = t + 256 * r;
        const float ba = b_a2[s];
#pragma unroll
        for (int bb = 0; bb < 8; bb++)
            g_ebuf[(size_t)(b0 + bb) * Sv + s] = __expf(acc[r][bb] + ba) * inv[bb];
    }
}

// ---------------------------------------------------------------------------
// K3: out[b,s,:] = sp + (write_value - sp) * a[b,s]. Streaming, ILP 4.
// ---------------------------------------------------------------------------
__global__ __launch_bounds__(256) void k3_write(const float* __restrict__ sp,
                                                float* __restrict__ out)
{
    const size_t base = (size_t)blockIdx.x * 1024 + threadIdx.x;  // float4 units
#pragma unroll
    for (int j = 0; j < 4; j++) {
        const size_t gi = base + (size_t)j * 256;
        const size_t row = gi >> 4;
        const int b = (int)(row >> 11);
        const float a = __ldg(&g_ebuf[row]);
        const float4 x = __ldcs(((const float4*)sp) + gi);
        const float4 w = __ldg(((const float4*)g_wvbuf) + (size_t)b * 16 + (gi & 15));
        float4 o;
        o.x = x.x + (w.x - x.x) * a;
        o.y = x.y + (w.y - x.y) * a;
        o.z = x.z + (w.z - x.z) * a;
        o.w = x.w + (w.w - x.w) * a;
        __stcs(((float4*)out) + gi, o);
    }
}

extern "C" void kernel_launch(void* const* d_in, const int* in_sizes, int n_in,
                              void* d_out, int out_size)
{
    (void)in_sizes; (void)n_in; (void)out_size;
    const float* query   = (const float*)d_in[0];
    const float* sp      = (const float*)d_in[1];
    const float* wq      = (const float*)d_in[2];
    const float* wk      = (const float*)d_in[3];
    const float* wv      = (const float*)d_in[4];
    const float* bq      = (const float*)d_in[5];
    const float* bk      = (const float*)d_in[6];
    const float* bv      = (const float*)d_in[7];
    const float* wo      = (const float*)d_in[8];
    const float* bo      = (const float*)d_in[9];
    const float* w_write = (const float*)d_in[10];
    const float* b_write = (const float*)d_in[11];
    const float* w_a1    = (const float*)d_in[12];
    const float* b_a1    = (const float*)d_in[13];
    const float* w_a2    = (const float*)d_in[14];
    const float* b_a2    = (const float*)d_in[15];
    float* out = (float*)d_out;

    const int k1_dyn = 8 * NSTAGE * 128 * (int)sizeof(float);   // 65536 bytes
    cudaFuncSetAttribute(k1_attn, cudaFuncAttributeMaxDynamicSharedMemorySize, k1_dyn);

    k1_attn<<<Bv, 256, k1_dyn>>>(query, sp, wq, wk, wv, bq, bk, bv, wo, bo,
                                 w_write, b_write, w_a1, b_a1);
    k2_addr<<<Bv / 8, 256>>>(w_a2, b_a2);
    k3_write<<<(Bv * Sv * Dv / 4) / 1024, 256>>>(sp, out);
}

// round 13
// speedup vs baseline: 1.0578x; 1.0578x over previous
#include <cuda_runtime.h>
#include <math.h>

#define Bv 1024
#define Sv 2048
#define Dv 64
#define Hv 4
#define HDv 16

#define NSTAGE 12      // smem ring stages per warp
#define LOOKAHEAD 8    // chunks in flight

// Scratch (no cudaMalloc allowed) — static device globals.
__device__ float g_hbuf[Bv * 128];        // relu(value @ w_a1.T + b_a1)
__device__ float g_wvbuf[Bv * Dv];        // write_value per batch
__device__ float g_ebuf[(size_t)Bv * Sv]; // NORMALIZED address a[b,s]

__device__ __forceinline__ void cp_async16(void* smem_dst, const void* gsrc) {
    unsigned sd = (unsigned)__cvta_generic_to_shared(smem_dst);
    asm volatile("cp.async.cg.shared.global [%0], [%1], 16;\n"
                 :: "r"(sd), "l"(gsrc) : "memory");
}
#define CP_COMMIT() asm volatile("cp.async.commit_group;\n" ::: "memory")
#define CP_WAIT6()  asm volatile("cp.async.wait_group 6;\n" ::: "memory")
#define CP_WAIT0()  asm volatile("cp.async.wait_group 0;\n" ::: "memory")

// ---- packed f32x2 helpers (sm_103a paired-FP32 pipe) ----
typedef unsigned long long u64t;
__device__ __forceinline__ u64t pk2(float a, float b) {
    u64t r; asm("mov.b64 %0, {%1, %2};" : "=l"(r) : "f"(a), "f"(b)); return r;
}
__device__ __forceinline__ void unpk2(float& a, float& b, u64t p) {
    asm("mov.b64 {%0, %1}, %2;" : "=f"(a), "=f"(b) : "l"(p));
}
__device__ __forceinline__ u64t mul2(u64t a, u64t b) {
    u64t r; asm("mul.rn.f32x2 %0, %1, %2;" : "=l"(r) : "l"(a), "l"(b)); return r;
}
__device__ __forceinline__ void fma2(u64t& d, u64t a, u64t b) {
    asm("fma.rn.f32x2 %0, %1, %2, %0;" : "+l"(d) : "l"(a), "l"(b));
}

// ---- bf16x2 shuffle packing: halve SHFL count across the chunk pair ----
// pack(hi, lo): r[31:16]=bf16(hi), r[15:0]=bf16(lo)
__device__ __forceinline__ unsigned bpk(float hi, float lo) {
    unsigned r; asm("cvt.rn.bf16x2.f32 %0, %1, %2;" : "=r"(r) : "f"(hi), "f"(lo));
    return r;
}
__device__ __forceinline__ float blo(unsigned p) { return __uint_as_float(p << 16); }
__device__ __forceinline__ float bhi(unsigned p) { return __uint_as_float(p & 0xffff0000u); }

#define LOG2E 1.4426950408889634f

// ---------------------------------------------------------------------------
// K1 (R12): R10 champion structure (unroll-2 chain interleaving, per-warp
// cp.async ring) + bf16x2-PACKED SHUFFLE REDUCTION. ncu across 6 variants
// shows L1tex/MIO at 70-74% while DRAM idles at ~40%: k1 is bound by MIO ops
// per byte (LDGSTS+LDS+SHFL share the unit). The chunk pair gives natural
// 2-wide packing: every reduction/allgather SHFL round carries both chunks'
// values in one bf16x2 register -> SHFL per 2KB drops 14 -> 7. Only the
// received halves are bf16-rounded (~2e-3 on scores); per-row weight noise
// averages down by sqrt(2048) in the attention mean => ~1e-5 final rel_err.
// ---------------------------------------------------------------------------
__global__ __launch_bounds__(256, 2) void k1_attn(
    const float* __restrict__ query, const float* __restrict__ sp,
    const float* __restrict__ wq, const float* __restrict__ wk,
    const float* __restrict__ wv, const float* __restrict__ bq,
    const float* __restrict__ bk, const float* __restrict__ bv,
    const float* __restrict__ wo, const float* __restrict__ bo,
    const float* __restrict__ w_write, const float* __restrict__ b_write,
    const float* __restrict__ w_a1, const float* __restrict__ b_a1)
{
    extern __shared__ float dyn[];   // 8 warps * 12 stages * 272 floats (104.4KB)
    __shared__ float s_q[Dv];
    __shared__ float s_qv[Dv];
    __shared__ float s_qk[Hv * Dv];
    __shared__ float s_c[Hv];
    __shared__ float s_pl[32 * Hv];
    __shared__ float s_wvec[Hv * Dv];
    __shared__ float s_ctx[Dv];
    __shared__ float s_val[Dv];

    const int b = blockIdx.x;
    const int t = threadIdx.x;
    const int warp = t >> 5, lane = t & 31;
    const int g = lane >> 3, sub = lane & 7;
    const float* spb = sp + (size_t)b * Sv * Dv;

    float* wbase = dyn + warp * (NSTAGE * 272);     // this warp's private ring
    float* lbase = wbase + g * 68 + sub * 4;        // lane's write slot (per stage)
    const float* src0 = spb + ((size_t)warp * 256 + g) * 64 + sub * 4;

    // ---- prologue: issue chunks 0..7 (4 rows = 1KB each; 2 cp.async/lane) ----
#pragma unroll
    for (int c = 0; c < LOOKAHEAD; c++) {
        float* dst = lbase + c * 272;
        const float* src = src0 + (size_t)c * 256;
        cp_async16(dst, src);
        cp_async16(dst + 32, src + 32);
        CP_COMMIT();
    }

    // ---- q projection (overlaps with in-flight loads) ----
    if (t < Dv) s_q[t] = query[(size_t)b * Dv + t];
    __syncthreads();
    if (t < Dv) {
        float acc = bq[t];
        const float* wr = wq + t * Dv;
#pragma unroll
        for (int j = 0; j < Dv; j++) acc += __ldg(wr + j) * s_q[j];
        s_qv[t] = acc;
    }
    __syncthreads();

    // ---- folded score vectors: qk_h[j] = 0.25 * sum_t qv[16h+t]*wk[16h+t,j] ----
    {
        const int h = t >> 6, j = t & 63;
        float acc = 0.f;
#pragma unroll
        for (int tt = 0; tt < HDv; tt++)
            acc += s_qv[h * HDv + tt] * __ldg(&wk[(h * HDv + tt) * Dv + j]);
        s_qk[h * Dv + j] = 0.25f * acc;
        if (t < Hv) {
            float c = 0.f;
#pragma unroll
            for (int tt = 0; tt < HDv; tt++) c += s_qv[t * HDv + tt] * __ldg(&bk[t * HDv + tt]);
            s_c[t] = 0.25f * c;
        }
    }
    __syncthreads();

    // lane's dims: k<4 -> 4*sub+k ; k>=4 -> 32+4*sub+(k-4); packed pairs
    u64t qk2[Hv][4];
#pragma unroll
    for (int h = 0; h < Hv; h++) {
        float r[8];
#pragma unroll
        for (int k = 0; k < 8; k++) {
            int d = (k < 4) ? (4 * sub + k) : (32 + 4 * sub + k - 4);
            r[k] = s_qk[h * Dv + d];
        }
#pragma unroll
        for (int kk = 0; kk < 4; kk++) qk2[h][kk] = pk2(r[2 * kk], r[2 * kk + 1]);
    }
    const int base = sub & 3;                 // head this lane owns post-reduction
    const float cprem = s_c[base] * LOG2E;
    const bool b0 = (sub & 1) != 0;
    const bool b1 = (sub & 2) != 0;

    u64t u2[Hv][4];                            // u2[j] accumulates head (base^j)
    float ls[Hv];
#pragma unroll
    for (int j = 0; j < Hv; j++) {
        ls[j] = 0.f;
#pragma unroll
        for (int kk = 0; kk < 4; kk++) u2[j][kk] = 0ull;
    }

    // ---- main loop: 32 iterations x 2 chunks, interleaved chains ----
    int st = 0;                 // stage of chunk c   (c even; st in {0,2,..,10})
    int nst = LOOKAHEAD;        // stage of chunk c+8
#pragma unroll 1
    for (int c = 0; c < 64; c += 2) {
        CP_WAIT6();                      // chunks c, c+1 complete for THIS thread

        // issue chunks c+8, c+9 (enter memory system before compute)
        if (c + 8 < 64) {
            cp_async16(lbase + nst * 272, src0 + (size_t)(c + 8) * 256);
            cp_async16(lbase + nst * 272 + 32, src0 + (size_t)(c + 8) * 256 + 32);
        }
        CP_COMMIT();
        if (c + 9 < 64) {
            cp_async16(lbase + (nst + 1) * 272, src0 + (size_t)(c + 9) * 256);
            cp_async16(lbase + (nst + 1) * 272 + 32, src0 + (size_t)(c + 9) * 256 + 32);
        }
        CP_COMMIT();

        // phase 1: load both chunks' data
        u64t XP[2][4];
#pragma unroll
        for (int j = 0; j < 2; j++) {
            const float4* tp = (const float4*)(wbase + (st + j) * 272);
            float4 a0 = tp[g * 17 + sub];
            float4 a1 = tp[g * 17 + 8 + sub];
            XP[j][0] = pk2(a0.x, a0.y); XP[j][1] = pk2(a0.z, a0.w);
            XP[j][2] = pk2(a1.x, a1.y); XP[j][3] = pk2(a1.z, a1.w);
        }

        // phase 2: score partials for both chunks
        float V[2][Hv];
#pragma unroll
        for (int j = 0; j < 2; j++)
#pragma unroll
            for (int h = 0; h < Hv; h++) {
                u64t acc = mul2(qk2[h][0], XP[j][0]);
                fma2(acc, qk2[h][1], XP[j][1]);
                fma2(acc, qk2[h][2], XP[j][2]);
                fma2(acc, qk2[h][3], XP[j][3]);
                float lo, hi; unpk2(lo, hi, acc);
                V[j][h] = lo + hi;
            }

        // phase 3: reduce-scatter, bf16x2-packed across the chunk pair.
        // Round ^2: send (s0,s1), keep the complementary pair.
        float a0s[2], a1s[2];
        {
            float s0[2], s1[2];
#pragma unroll
            for (int j = 0; j < 2; j++) {
                s0[j] = b1 ? V[j][0] : V[j][2];
                s1[j] = b1 ? V[j][1] : V[j][3];
            }
            unsigned P0 = bpk(s0[1], s0[0]);
            unsigned P1 = bpk(s1[1], s1[0]);
            unsigned R0 = __shfl_xor_sync(0xffffffffu, P0, 2);
            unsigned R1 = __shfl_xor_sync(0xffffffffu, P1, 2);
            a0s[0] = (b1 ? V[0][2] : V[0][0]) + blo(R0);   // head 2*b1
            a0s[1] = (b1 ? V[1][2] : V[1][0]) + bhi(R0);
            a1s[0] = (b1 ? V[0][3] : V[0][1]) + blo(R1);   // head 2*b1+1
            a1s[1] = (b1 ? V[1][3] : V[1][1]) + bhi(R1);
        }
        // Round ^1 then ^4, both packed.
        float S[2];
        {
            float s2[2];
#pragma unroll
            for (int j = 0; j < 2; j++) s2[j] = b0 ? a0s[j] : a1s[j];
            unsigned P2 = bpk(s2[1], s2[0]);
            unsigned R2 = __shfl_xor_sync(0xffffffffu, P2, 1);
            S[0] = (b0 ? a1s[0] : a0s[0]) + blo(R2);
            S[1] = (b0 ? a1s[1] : a0s[1]) + bhi(R2);
            unsigned P3 = bpk(S[1], S[0]);
            unsigned R3 = __shfl_xor_sync(0xffffffffu, P3, 4);
            S[0] += blo(R3);
            S[1] += bhi(R3);
        }

        // phase 4: exp once per head (fp32), bf16x2-packed 3-SHFL allgather
        float Q[2][4];
        {
            float q0[2];
#pragma unroll
            for (int j = 0; j < 2; j++) q0[j] = exp2f(__fmaf_rn(S[j], LOG2E, cprem));
            unsigned Q0p = bpk(q0[1], q0[0]);
            unsigned Q1p = __shfl_xor_sync(0xffffffffu, Q0p, 1);
            unsigned Q2p = __shfl_xor_sync(0xffffffffu, Q0p, 2);
            unsigned Q3p = __shfl_xor_sync(0xffffffffu, Q1p, 2);
            Q[0][0] = q0[0];     Q[1][0] = q0[1];
            Q[0][1] = blo(Q1p);  Q[1][1] = bhi(Q1p);
            Q[0][2] = blo(Q2p);  Q[1][2] = bhi(Q2p);
            Q[0][3] = blo(Q3p);  Q[1][3] = bhi(Q3p);
        }

        // phase 5: accumulate both chunks
#pragma unroll
        for (int j = 0; j < 2; j++) {
#pragma unroll
            for (int hh = 0; hh < Hv; hh++) {
                ls[hh] += Q[j][hh];
                u64t qq = pk2(Q[j][hh], Q[j][hh]);
                fma2(u2[hh][0], qq, XP[j][0]);
                fma2(u2[hh][1], qq, XP[j][1]);
                fma2(u2[hh][2], qq, XP[j][2]);
                fma2(u2[hh][3], qq, XP[j][3]);
            }
        }

        st += 2;  if (st >= NSTAGE) st -= NSTAGE;
        nst += 2; if (nst >= NSTAGE) nst -= NSTAGE;
    }
    CP_WAIT0();
    __syncthreads();

    // ---- combine 32 group partials (dyn aliased; needs 8192 floats) ----
    // u2[j]/ls[j] correspond to REAL head (base^j): permute on store.
    float* s_part = dyn;
    const int pg = warp * 4 + g;
    if (sub == 0) {                 // base=0 -> identity permutation
#pragma unroll
        for (int j = 0; j < Hv; j++) s_pl[pg * 4 + j] = ls[j];
    }
#pragma unroll
    for (int j = 0; j < Hv; j++) {
        const int h = base ^ j;     // real head
#pragma unroll
        for (int kk = 0; kk < 4; kk++) {
            float lo, hi; unpk2(lo, hi, u2[j][kk]);
            int k0 = 2 * kk, k1 = 2 * kk + 1;
            int d0 = (k0 < 4) ? (4 * sub + k0) : (32 + 4 * sub + k0 - 4);
            int d1 = (k1 < 4) ? (4 * sub + k1) : (32 + 4 * sub + k1 - 4);
            s_part[(pg * 4 + h) * 64 + d0] = lo;
            s_part[(pg * 4 + h) * 64 + d1] = hi;
        }
    }
    __syncthreads();
    {
        const int h = t >> 6, d = t & 63;
        float U = 0.f;
#pragma unroll
        for (int p = 0; p < 32; p++) U += s_part[(p * 4 + h) * 64 + d];
        float L = 0.f;
#pragma unroll
        for (int p = 0; p < 32; p++) L += s_pl[p * 4 + h];
        s_wvec[h * 64 + d] = U / L;   // attn-weighted mean of sp rows
    }
    __syncthreads();

    // ---- tiny per-batch matvec chain (weights straight from global/L2) ----
    if (t < Dv) {
        float acc = bv[t];
        const int h = t >> 4;
        const float* wr = wv + t * Dv;
#pragma unroll
        for (int j = 0; j < Dv; j++) acc += __ldg(wr + j) * s_wvec[h * 64 + j];
        s_ctx[t] = acc;
    }
    __syncthreads();
    if (t < Dv) {
        float acc = bo[t];
        const float* wr = wo + t * Dv;
#pragma unroll
        for (int j = 0; j < Dv; j++) acc += __ldg(wr + j) * s_ctx[j];
        s_val[t] = acc;
    }
    __syncthreads();
    if (t < 128) {
        float acc = b_a1[t];
        const float* wr = w_a1 + t * Dv;
#pragma unroll
        for (int j = 0; j < Dv; j++) acc += __ldg(wr + j) * s_val[j];
        g_hbuf[(size_t)b * 128 + t] = fmaxf(acc, 0.f);
    }
    if (t >= 128 && t < 128 + Dv) {
        const int o = t - 128;
        float acc = b_write[o];
        const float* wr = w_write + o * Dv;
#pragma unroll
        for (int j = 0; j < Dv; j++) acc += __ldg(wr + j) * s_val[j];
        g_wvbuf[(size_t)b * Dv + o] = acc;
    }
}

// ---------------------------------------------------------------------------
// K2: address logits GEMM (1024 x 2048 x 128) + softmax. Writes NORMALIZED
// address a[b,s] into g_ebuf (the CTA owns the full per-batch denominator).
// ---------------------------------------------------------------------------
__global__ __launch_bounds__(256) void k2_addr(const float* __restrict__ w_a2,
                                               const float* __restrict__ b_a2)
{
    const int b0 = blockIdx.x * 8;
    const int t = threadIdx.x;
    __shared__ float hs[8 * 128];
    __shared__ float sden[8];

    for (int idx = t; idx < 1024; idx += 256) hs[idx] = g_hbuf[(size_t)b0 * 128 + idx];
    if (t < 8) sden[t] = 0.f;
    __syncthreads();

    float acc[8][8];
#pragma unroll
    for (int r = 0; r < 8; r++)
#pragma unroll
        for (int bb = 0; bb < 8; bb++) acc[r][bb] = 0.f;

    const float4* w4 = (const float4*)w_a2;
    const float4* h4 = (const float4*)hs;
#pragma unroll 1
    for (int k8 = 0; k8 < 16; k8++) {
        float4 ha[8], hb[8];
#pragma unroll
        for (int bb = 0; bb < 8; bb++) {
            ha[bb] = h4[bb * 32 + 2 * k8];
            hb[bb] = h4[bb * 32 + 2 * k8 + 1];
        }
#pragma unroll
        for (int r = 0; r < 8; r++) {
            const int s = t + 256 * r;
            float4 wa = w4[(size_t)s * 32 + 2 * k8];
            float4 wb = w4[(size_t)s * 32 + 2 * k8 + 1];
#pragma unroll
            for (int bb = 0; bb < 8; bb++) {
                acc[r][bb] += wa.x * ha[bb].x + wa.y * ha[bb].y +
                              wa.z * ha[bb].z + wa.w * ha[bb].w +
                              wb.x * hb[bb].x + wb.y * hb[bb].y +
                              wb.z * hb[bb].z + wb.w * hb[bb].w;
            }
        }
    }

    // pass 1: per-batch exp-sum (logits small -> safe without max-sub)
    float psum[8];
#pragma unroll
    for (int bb = 0; bb < 8; bb++) psum[bb] = 0.f;
#pragma unroll
    for (int r = 0; r < 8; r++) {
        const float ba = b_a2[t + 256 * r];
#pragma unroll
        for (int bb = 0; bb < 8; bb++) psum[bb] += __expf(acc[r][bb] + ba);
    }
#pragma unroll
    for (int off = 16; off; off >>= 1)
#pragma unroll
        for (int bb = 0; bb < 8; bb++)
            psum[bb] += __shfl_xor_sync(0xffffffffu, psum[bb], off);
    if ((t & 31) == 0) {
#pragma unroll
        for (int bb = 0; bb < 8; bb++) atomicAdd(&sden[bb], psum[bb]);
    }
    __syncthreads();

    float inv[8];
#pragma unroll
    for (int bb = 0; bb < 8; bb++) inv[bb] = 1.f / sden[bb];

    // pass 2: recompute exp (deterministic), write normalized a
#pragma unroll
    for (int r = 0; r < 8; r++) {
        const int s = t + 256 * r;
        const float ba = b_a2[s];
#pragma unroll
        for (int bb = 0; bb < 8; bb++)
            g_ebuf[(size_t)(b0 + bb) * Sv + s] = __expf(acc[r][bb] + ba) * inv[bb];
    }
}

// ---------------------------------------------------------------------------
// K3: out[b,s,:] = sp + (write_value - sp) * a[b,s]. Streaming, ILP 4.
// ---------------------------------------------------------------------------
__global__ __launch_bounds__(256) void k3_write(const float* __restrict__ sp,
                                                float* __restrict__ out)
{
    const size_t base = (size_t)blockIdx.x * 1024 + threadIdx.x;  // float4 units
#pragma unroll
    for (int j = 0; j < 4; j++) {
        const size_t gi = base + (size_t)j * 256;
        const size_t row = gi >> 4;
        const int b = (int)(row >> 11);
        const float a = __ldg(&g_ebuf[row]);
        const float4 x = __ldcs(((const float4*)sp) + gi);
        const float4 w = __ldg(((const float4*)g_wvbuf) + (size_t)b * 16 + (gi & 15));
        float4 o;
        o.x = x.x + (w.x - x.x) * a;
        o.y = x.y + (w.y - x.y) * a;
        o.z = x.z + (w.z - x.z) * a;
        o.w = x.w + (w.w - x.w) * a;
        __stcs(((float4*)out) + gi, o);
    }
}

extern "C" void kernel_launch(void* const* d_in, const int* in_sizes, int n_in,
                              void* d_out, int out_size)
{
    (void)in_sizes; (void)n_in; (void)out_size;
    const float* query   = (const float*)d_in[0];
    const float* sp      = (const float*)d_in[1];
    const float* wq      = (const float*)d_in[2];
    const float* wk      = (const float*)d_in[3];
    const float* wv      = (const float*)d_in[4];
    const float* bq      = (const float*)d_in[5];
    const float* bk      = (const float*)d_in[6];
    const float* bv      = (const float*)d_in[7];
    const float* wo      = (const float*)d_in[8];
    const float* bo      = (const float*)d_in[9];
    const float* w_write = (const float*)d_in[10];
    const float* b_write = (const float*)d_in[11];
    const float* w_a1    = (const float*)d_in[12];
    const float* b_a1    = (const float*)d_in[13];
    const float* w_a2    = (const float*)d_in[14];
    const float* b_a2    = (const float*)d_in[15];
    float* out = (float*)d_out;

    const int k1_dyn = 8 * NSTAGE * 272 * (int)sizeof(float);   // 104448 bytes
    cudaFuncSetAttribute(k1_attn, cudaFuncAttributeMaxDynamicSharedMemorySize, k1_dyn);

    k1_attn<<<Bv, 256, k1_dyn>>>(query, sp, wq, wk, wv, bq, bk, bv, wo, bo,
                                 w_write, b_write, w_a1, b_a1);
    k2_addr<<<Bv / 8, 256>>>(w_a2, b_a2);
    k3_write<<<(Bv * Sv * Dv / 4) / 1024, 256>>>(sp, out);
}